// round 1
// baseline (speedup 1.0000x reference)
#include <cuda_runtime.h>
#include <math.h>
#include <float.h>

// Problem constants
#define Bv   8
#define Lv   4096
#define LP   4097          // L + 1 (bias token)
#define KDv  512
#define EDv  1024
#define Hv   8
#define DK   64            // KD / H
#define DV   128           // ED / H
#define BH   64            // B * H
#define KCHUNK   (LP * DK)          // 262208 floats per (b,h) key chunk
#define VCHUNK   (LP * DV)          // 524416 floats per (b,h) value chunk
#define KBATCH   (Lv * KDv)         // 2097152 floats of real keys per batch
#define VBATCH   (Lv * EDv)         // 4194304 floats of real values per batch
#define NT   64                     // j-tiles for the AV kernel
#define TILE 65                     // ceil(4097 / 64)

// Scratch (allocation-free rule: __device__ globals)
__device__ float g_scores[BH * LP];           // ~1.05 MB
__device__ float g_partial[BH * NT * DV];     // 2 MB

// ---------------------------------------------------------------------------
// Kernel 1: scores[bh, j] = dot64(Q[h], K[bh, j, :]) * w[h,j] + bias[h,j]
// One warp per row. Row = 64 contiguous floats (256B) -> float2 per lane.
// ---------------------------------------------------------------------------
__global__ void k_scores(const float* __restrict__ keys,
                         const float* __restrict__ k_bias,
                         const float* __restrict__ query,
                         const float* __restrict__ sw,
                         const float* __restrict__ sb) {
    int gw   = (blockIdx.x * blockDim.x + threadIdx.x) >> 5;
    int lane = threadIdx.x & 31;
    if (gw >= BH * LP) return;
    int bh = gw / LP;
    int j  = gw - bh * LP;
    int b  = bh >> 3;
    int h  = bh & 7;

    // raw-view addressing: within-batch flat offset of this row
    int f = h * KCHUNK + j * DK;
    const float* krow = (f >= KBATCH) ? (k_bias + (f - KBATCH))
                                      : (keys + b * KBATCH + f);

    float2 k2 = *(const float2*)(krow + lane * 2);
    float2 q2 = *(const float2*)(query + h * DK + lane * 2);
    float s = k2.x * q2.x + k2.y * q2.y;
    #pragma unroll
    for (int o = 16; o > 0; o >>= 1)
        s += __shfl_xor_sync(0xffffffffu, s, o);

    if (lane == 0) {
        int wi = h * LP + j;
        g_scores[gw] = s * __ldg(sw + wi) + __ldg(sb + wi);
    }
}

// ---------------------------------------------------------------------------
// Kernel 2: in-place softmax over each row of g_scores (64 rows x 4097).
// 512 threads/block, one block per row, values held in registers.
// ---------------------------------------------------------------------------
__device__ __forceinline__ float block_reduce(float v, float* sh, bool do_max) {
    int lane = threadIdx.x & 31, warp = threadIdx.x >> 5;
    #pragma unroll
    for (int o = 16; o > 0; o >>= 1) {
        float t = __shfl_xor_sync(0xffffffffu, v, o);
        v = do_max ? fmaxf(v, t) : (v + t);
    }
    if (lane == 0) sh[warp] = v;
    __syncthreads();
    int nw = blockDim.x >> 5;
    if (warp == 0) {
        v = (lane < nw) ? sh[lane] : (do_max ? -FLT_MAX : 0.0f);
        #pragma unroll
        for (int o = 16; o > 0; o >>= 1) {
            float t = __shfl_xor_sync(0xffffffffu, v, o);
            v = do_max ? fmaxf(v, t) : (v + t);
        }
        if (lane == 0) sh[0] = v;
    }
    __syncthreads();
    v = sh[0];
    __syncthreads();
    return v;
}

__global__ void k_softmax() {
    __shared__ float sh[32];
    float* row = g_scores + blockIdx.x * LP;

    float v[9];
    float m = -FLT_MAX;
    #pragma unroll
    for (int k = 0; k < 9; k++) {
        int j = threadIdx.x + k * 512;
        v[k] = (j < LP) ? row[j] : -FLT_MAX;
        m = fmaxf(m, v[k]);
    }
    m = block_reduce(m, sh, true);

    float s = 0.0f;
    #pragma unroll
    for (int k = 0; k < 9; k++) {
        int j = threadIdx.x + k * 512;
        v[k] = (j < LP) ? expf(v[k] - m) : 0.0f;
        s += v[k];
    }
    s = block_reduce(s, sh, false);
    float inv = 1.0f / s;

    #pragma unroll
    for (int k = 0; k < 9; k++) {
        int j = threadIdx.x + k * 512;
        if (j < LP) row[j] = v[k] * inv;
    }
}

// ---------------------------------------------------------------------------
// Kernel 3: partial[bh, tile, d] = sum_{j in tile} p[bh,j] * V[bh, j, d]
// grid = (NT, BH), 128 threads = 4 warps. Each warp streams whole 512B V rows
// (float4 per lane), rows interleaved mod 4 across warps. Shared reduce at end.
// ---------------------------------------------------------------------------
__global__ void k_av(const float* __restrict__ values,
                     const float* __restrict__ v_bias) {
    int tile = blockIdx.x;
    int bh   = blockIdx.y;
    int b = bh >> 3, h = bh & 7;
    int r4 = threadIdx.x >> 5;     // warp id 0..3 -> row phase
    int c  = threadIdx.x & 31;     // float4 column 0..31

    const float* p = g_scores + bh * LP;
    int j0 = tile * TILE;
    int j1 = min(j0 + TILE, LP);

    float4 acc = make_float4(0.f, 0.f, 0.f, 0.f);
    for (int j = j0 + r4; j < j1; j += 4) {
        float pj = __ldg(p + j);
        int f = h * VCHUNK + j * DV;
        const float* vrow = (f >= VBATCH) ? (v_bias + (f - VBATCH))
                                          : (values + b * VBATCH + f);
        float4 vv = *(const float4*)(vrow + c * 4);
        acc.x += pj * vv.x;
        acc.y += pj * vv.y;
        acc.z += pj * vv.z;
        acc.w += pj * vv.w;
    }

    __shared__ float4 red[4][32];
    red[r4][c] = acc;
    __syncthreads();
    if (r4 == 0) {
        float4 a = red[0][c], x = red[1][c], y = red[2][c], z = red[3][c];
        a.x += x.x + y.x + z.x;
        a.y += x.y + y.y + z.y;
        a.z += x.z + y.z + z.z;
        a.w += x.w + y.w + z.w;
        *(float4*)(g_partial + (bh * NT + tile) * DV + c * 4) = a;
    }
}

// ---------------------------------------------------------------------------
// Kernel 4: reduce partials + LayerNorm over 1024, one block per batch.
// ---------------------------------------------------------------------------
__global__ void k_ln(const float* __restrict__ gamma,
                     const float* __restrict__ beta,
                     float* __restrict__ out) {
    __shared__ float sh_s[32];
    __shared__ float sh_q[32];
    int b = blockIdx.x;
    int t = threadIdx.x;           // 0..1023
    int h = t >> 7, d = t & 127;
    int bh = b * 8 + h;

    float a = 0.0f;
    const float* pp = g_partial + bh * (NT * DV) + d;
    #pragma unroll
    for (int k = 0; k < NT; k++) a += pp[k * DV];

    // block-wide sum & sumsq over 1024 values
    float s = a, q = a * a;
    int lane = t & 31, warp = t >> 5;
    #pragma unroll
    for (int o = 16; o > 0; o >>= 1) {
        s += __shfl_xor_sync(0xffffffffu, s, o);
        q += __shfl_xor_sync(0xffffffffu, q, o);
    }
    if (lane == 0) { sh_s[warp] = s; sh_q[warp] = q; }
    __syncthreads();
    if (warp == 0) {
        s = sh_s[lane];
        q = sh_q[lane];
        #pragma unroll
        for (int o = 16; o > 0; o >>= 1) {
            s += __shfl_xor_sync(0xffffffffu, s, o);
            q += __shfl_xor_sync(0xffffffffu, q, o);
        }
        if (lane == 0) { sh_s[0] = s; sh_q[0] = q; }
    }
    __syncthreads();
    float mean = sh_s[0] * (1.0f / EDv);
    float var  = sh_q[0] * (1.0f / EDv) - mean * mean;
    float inv  = rsqrtf(var + 1e-5f);

    out[b * EDv + t] = (a - mean) * inv * __ldg(gamma + t) + __ldg(beta + t);
}

// ---------------------------------------------------------------------------
// Launch: inputs in metadata order:
// keys, values, query, k_bias, v_bias, softmax_weight, softmax_bias, gamma, beta
// ---------------------------------------------------------------------------
extern "C" void kernel_launch(void* const* d_in, const int* in_sizes, int n_in,
                              void* d_out, int out_size) {
    const float* keys   = (const float*)d_in[0];
    const float* values = (const float*)d_in[1];
    const float* query  = (const float*)d_in[2];
    const float* k_bias = (const float*)d_in[3];
    const float* v_bias = (const float*)d_in[4];
    const float* sw     = (const float*)d_in[5];
    const float* sb     = (const float*)d_in[6];
    const float* gamma  = (const float*)d_in[7];
    const float* beta   = (const float*)d_in[8];
    float* out = (float*)d_out;

    // K1: one warp per (bh, j) row; 256 threads = 8 warps per block
    int nrows = BH * LP;                   // 262208
    int blocks1 = (nrows + 7) / 8;
    k_scores<<<blocks1, 256>>>(keys, k_bias, query, sw, sb);

    // K2: softmax per bh row
    k_softmax<<<BH, 512>>>();

    // K3: attn @ V partials
    dim3 g3(NT, BH);
    k_av<<<g3, 128>>>(values, v_bias);

    // K4: reduce + layernorm
    k_ln<<<Bv, 1024>>>(gamma, beta, out);
}

// round 2
// speedup vs baseline: 1.3375x; 1.3375x over previous
#include <cuda_runtime.h>
#include <math.h>
#include <float.h>

// Problem constants
#define Bv   8
#define Lv   4096
#define LP   4097          // L + 1 (bias token)
#define KDv  512
#define EDv  1024
#define Hv   8
#define DK   64            // KD / H
#define DV   128           // ED / H
#define BH   64            // B * H
#define KCHUNK   (LP * DK)          // floats per (b,h) key chunk in raw view
#define VCHUNK   (LP * DV)          // floats per (b,h) value chunk in raw view
#define KBATCH   (Lv * KDv)         // real key floats per batch
#define VBATCH   (Lv * EDv)         // real value floats per batch
#define NT   16                     // j-tiles for the AV kernel
#define TILE 257                    // ceil(4097 / 16)
#define NPAIR 2049                  // ceil(4097 / 2) row-pairs per bh

// Scratch (allocation-free rule: __device__ globals)
__device__ float g_scores[BH * LP];           // ~1.05 MB
__device__ float g_partial[BH * NT * DV];     // 512 KB

// ---------------------------------------------------------------------------
// Kernel 1: scores[bh, j] = dot64(Q[h], K[bh, j, :]) * w[h,j] + bias[h,j]
// One warp per PAIR of rows: lanes 0-15 row j, lanes 16-31 row j+1.
// Each lane loads float4 (512 B / warp), 4-shfl half-warp reduce.
// ---------------------------------------------------------------------------
__global__ void k_scores(const float* __restrict__ keys,
                         const float* __restrict__ k_bias,
                         const float* __restrict__ query,
                         const float* __restrict__ sw,
                         const float* __restrict__ sb) {
    int gw   = (blockIdx.x * blockDim.x + threadIdx.x) >> 5;
    int lane = threadIdx.x & 31;
    if (gw >= BH * NPAIR) return;
    int bh = gw / NPAIR;
    int p  = gw - bh * NPAIR;
    int b  = bh >> 3;
    int h  = bh & 7;

    int half = lane >> 4;          // which row of the pair
    int li   = lane & 15;          // float4 slot within row
    int j    = p * 2 + half;
    int jc   = min(j, LP - 1);     // clamp load for the odd tail row

    int f = h * KCHUNK + jc * DK + li * 4;
    const float* kp = (f >= KBATCH) ? (k_bias + (f - KBATCH))
                                    : (keys + b * KBATCH + f);

    float4 kv = __ldcs((const float4*)kp);
    float4 qv = *(const float4*)(query + h * DK + li * 4);
    float s = kv.x * qv.x + kv.y * qv.y + kv.z * qv.z + kv.w * qv.w;
    #pragma unroll
    for (int o = 8; o > 0; o >>= 1)
        s += __shfl_xor_sync(0xffffffffu, s, o);

    if (li == 0 && j < LP) {
        int wi = h * LP + j;
        g_scores[bh * LP + j] = s * __ldg(sw + wi) + __ldg(sb + wi);
    }
}

// ---------------------------------------------------------------------------
// Kernel 2: in-place softmax over each row of g_scores (64 rows x 4097).
// ---------------------------------------------------------------------------
__device__ __forceinline__ float block_reduce(float v, float* sh, bool do_max) {
    int lane = threadIdx.x & 31, warp = threadIdx.x >> 5;
    #pragma unroll
    for (int o = 16; o > 0; o >>= 1) {
        float t = __shfl_xor_sync(0xffffffffu, v, o);
        v = do_max ? fmaxf(v, t) : (v + t);
    }
    if (lane == 0) sh[warp] = v;
    __syncthreads();
    int nw = blockDim.x >> 5;
    if (warp == 0) {
        v = (lane < nw) ? sh[lane] : (do_max ? -FLT_MAX : 0.0f);
        #pragma unroll
        for (int o = 16; o > 0; o >>= 1) {
            float t = __shfl_xor_sync(0xffffffffu, v, o);
            v = do_max ? fmaxf(v, t) : (v + t);
        }
        if (lane == 0) sh[0] = v;
    }
    __syncthreads();
    v = sh[0];
    __syncthreads();
    return v;
}

__global__ void k_softmax() {
    __shared__ float sh[32];
    float* row = g_scores + blockIdx.x * LP;

    float v[9];
    float m = -FLT_MAX;
    #pragma unroll
    for (int k = 0; k < 9; k++) {
        int j = threadIdx.x + k * 512;
        v[k] = (j < LP) ? row[j] : -FLT_MAX;
        m = fmaxf(m, v[k]);
    }
    m = block_reduce(m, sh, true);

    float s = 0.0f;
    #pragma unroll
    for (int k = 0; k < 9; k++) {
        int j = threadIdx.x + k * 512;
        v[k] = (j < LP) ? expf(v[k] - m) : 0.0f;
        s += v[k];
    }
    s = block_reduce(s, sh, false);
    float inv = 1.0f / s;

    #pragma unroll
    for (int k = 0; k < 9; k++) {
        int j = threadIdx.x + k * 512;
        if (j < LP) row[j] = v[k] * inv;
    }
}

// ---------------------------------------------------------------------------
// Kernel 3: partial[bh, tile, d] = sum_{j in tile} p[bh,j] * V[bh, j, d]
// grid = (NT, BH), 256 threads = 8 warps. Each warp streams full 512B V rows
// (float4 per lane), rows interleaved mod 8 across warps. Shared reduce.
// ---------------------------------------------------------------------------
__global__ void k_av(const float* __restrict__ values,
                     const float* __restrict__ v_bias) {
    int tile = blockIdx.x;
    int bh   = blockIdx.y;
    int b = bh >> 3, h = bh & 7;
    int r8 = threadIdx.x >> 5;     // warp id 0..7 -> row phase
    int c  = threadIdx.x & 31;     // float4 column 0..31

    const float* p = g_scores + bh * LP;
    int j0 = tile * TILE;
    int j1 = min(j0 + TILE, LP);

    float4 acc = make_float4(0.f, 0.f, 0.f, 0.f);
    #pragma unroll 4
    for (int j = j0 + r8; j < j1; j += 8) {
        float pj = __ldg(p + j);
        int f = h * VCHUNK + j * DV;
        const float* vrow = (f >= VBATCH) ? (v_bias + (f - VBATCH))
                                          : (values + b * VBATCH + f);
        float4 vv = __ldcs((const float4*)(vrow + c * 4));
        acc.x += pj * vv.x;
        acc.y += pj * vv.y;
        acc.z += pj * vv.z;
        acc.w += pj * vv.w;
    }

    __shared__ float4 red[8][32];
    red[r8][c] = acc;
    __syncthreads();
    if (r8 == 0) {
        float4 a = red[0][c];
        #pragma unroll
        for (int w = 1; w < 8; w++) {
            float4 x = red[w][c];
            a.x += x.x; a.y += x.y; a.z += x.z; a.w += x.w;
        }
        *(float4*)(g_partial + (bh * NT + tile) * DV + c * 4) = a;
    }
}

// ---------------------------------------------------------------------------
// Kernel 4: reduce NT partials + LayerNorm over 1024, one block per batch.
// ---------------------------------------------------------------------------
__global__ void k_ln(const float* __restrict__ gamma,
                     const float* __restrict__ beta,
                     float* __restrict__ out) {
    __shared__ float sh_s[32];
    __shared__ float sh_q[32];
    int b = blockIdx.x;
    int t = threadIdx.x;           // 0..1023
    int h = t >> 7, d = t & 127;
    int bh = b * 8 + h;

    float a = 0.0f;
    const float* pp = g_partial + bh * (NT * DV) + d;
    #pragma unroll
    for (int k = 0; k < NT; k++) a += pp[k * DV];

    // block-wide sum & sumsq over 1024 values
    float s = a, q = a * a;
    int lane = t & 31, warp = t >> 5;
    #pragma unroll
    for (int o = 16; o > 0; o >>= 1) {
        s += __shfl_xor_sync(0xffffffffu, s, o);
        q += __shfl_xor_sync(0xffffffffu, q, o);
    }
    if (lane == 0) { sh_s[warp] = s; sh_q[warp] = q; }
    __syncthreads();
    if (warp == 0) {
        s = sh_s[lane];
        q = sh_q[lane];
        #pragma unroll
        for (int o = 16; o > 0; o >>= 1) {
            s += __shfl_xor_sync(0xffffffffu, s, o);
            q += __shfl_xor_sync(0xffffffffu, q, o);
        }
        if (lane == 0) { sh_s[0] = s; sh_q[0] = q; }
    }
    __syncthreads();
    float mean = sh_s[0] * (1.0f / EDv);
    float var  = sh_q[0] * (1.0f / EDv) - mean * mean;
    float inv  = rsqrtf(var + 1e-5f);

    out[b * EDv + t] = (a - mean) * inv * __ldg(gamma + t) + __ldg(beta + t);
}

// ---------------------------------------------------------------------------
// Launch: inputs in metadata order:
// keys, values, query, k_bias, v_bias, softmax_weight, softmax_bias, gamma, beta
// ---------------------------------------------------------------------------
extern "C" void kernel_launch(void* const* d_in, const int* in_sizes, int n_in,
                              void* d_out, int out_size) {
    const float* keys   = (const float*)d_in[0];
    const float* values = (const float*)d_in[1];
    const float* query  = (const float*)d_in[2];
    const float* k_bias = (const float*)d_in[3];
    const float* v_bias = (const float*)d_in[4];
    const float* sw     = (const float*)d_in[5];
    const float* sb     = (const float*)d_in[6];
    const float* gamma  = (const float*)d_in[7];
    const float* beta   = (const float*)d_in[8];
    float* out = (float*)d_out;

    // K1: one warp per row-pair; 256 threads = 8 warps per block
    int nwarps = BH * NPAIR;               // 131136
    int blocks1 = (nwarps + 7) / 8;
    k_scores<<<blocks1, 256>>>(keys, k_bias, query, sw, sb);

    // K2: softmax per bh row
    k_softmax<<<BH, 512>>>();

    // K3: attn @ V partials
    dim3 g3(NT, BH);
    k_av<<<g3, 256>>>(values, v_bias);

    // K4: reduce + layernorm
    k_ln<<<Bv, 1024>>>(gamma, beta, out);
}